// round 10
// baseline (speedup 1.0000x reference)
#include <cuda_runtime.h>
#include <cstdint>

#define NN 65536
#define NE 524288
#define NB 1024

// ---------------- scratch (device globals) ----------------------------------
__device__ float g_xr[NN * 96];     // tf32-rounded x
__device__ float g_AB1[NN * 256];
__device__ float g_AB2[NN * 128];
__device__ float g_z[NB * 192];     // tf32-rounded z
__device__ float g_t1[NB * 512];    // tf32-rounded t1
__device__ float g_t2[2 * NB * 256];
__device__ float g_actterm[NB * 256];
__device__ float g_W1[128 * 256];   // rows 0..95 tf32-rounded (x path)
__device__ float g_bias1[256];
__device__ float g_W2[128 * 128];   // tf32-rounded W2cat
__device__ float g_bias2[128];
__device__ float g_W1b[128 * 128];  // tf32(g1_w2)
__device__ float g_QW1[192 * 512];  // tf32-rounded
__device__ float g_Qb1[512];
__device__ float g_QW2a[256 * 256]; // tf32(q1_w2)
__device__ float g_QW2b[256 * 256]; // tf32(q2_w2)
__device__ int   g_deg[NN];
__device__ int   g_off[NN];
__device__ int   g_cur[NN];
__device__ int   g_csr[NE];
__device__ int   g_bsum[256];
__device__ int   g_boff[256];

// ---------------- tf32 helpers -------------------------------------------------

__device__ __forceinline__ float to_tf32(float x) {
    uint32_t u;
    asm("cvt.rna.tf32.f32 %0, %1;" : "=r"(u) : "f"(x));
    return __uint_as_float(u);
}

#define MMA_TF32(acc, af, bf)                                              \
    asm volatile(                                                          \
        "mma.sync.aligned.m16n8k8.row.col.f32.tf32.tf32.f32 "              \
        "{%0,%1,%2,%3}, {%4,%5,%6,%7}, {%8,%9}, {%0,%1,%2,%3};"            \
        : "+f"(acc[0]), "+f"(acc[1]), "+f"(acc[2]), "+f"(acc[3])           \
        : "r"(af[0]), "r"(af[1]), "r"(af[2]), "r"(af[3]),                  \
          "r"(bf[0]), "r"(bf[1]))

__device__ __forceinline__ void cp16(uint32_t s, const void* g) {
    asm volatile("cp.async.ca.shared.global [%0], [%1], 16;" :: "r"(s), "l"(g));
}

// ---------------- prep: pack + tf32-round GEMM weights ------------------------

__global__ void prep_kernel(const float* __restrict__ g1w1, const float* __restrict__ g1b1,
                            const float* __restrict__ g1w2,
                            const float* __restrict__ g2w1, const float* __restrict__ g2b1,
                            const float* __restrict__ q1w1, const float* __restrict__ q1b1,
                            const float* __restrict__ q1w2,
                            const float* __restrict__ q2w1, const float* __restrict__ q2b1,
                            const float* __restrict__ q2w2) {
    int idx = blockIdx.x * blockDim.x + threadIdx.x;
    if (idx < 24576) {   // W1 rows 0..95 (x path), tf32
        int k = idx >> 8, j = idx & 255;
        float v = (j < 128) ? g1w1[k * 128 + j] : g1w1[(k + 128) * 128 + (j - 128)];
        g_W1[idx] = to_tf32(v);
    } else if (idx < 24832) {
        int j = idx - 24576;
        g_bias1[j] = (j < 128) ? g1b1[j] : 0.f;
    } else if (idx < 41216) {
        int i2 = idx - 24832;
        int k = i2 >> 7, j = i2 & 127;
        float v = (j < 64) ? g2w1[k * 64 + j] : g2w1[(k + 128) * 64 + (j - 64)];
        g_W2[i2] = to_tf32(v);
    } else if (idx < 41344) {
        int j = idx - 41216;
        g_bias2[j] = (j < 64) ? g2b1[j] : 0.f;
    } else if (idx < 139648) {
        int i2 = idx - 41344;
        int k = i2 / 512, c = i2 & 511;
        float v = (c < 256) ? q1w1[k * 256 + c] : q2w1[k * 256 + (c - 256)];
        g_QW1[i2] = to_tf32(v);
    } else if (idx < 140160) {
        int j = idx - 139648;
        g_Qb1[j] = (j < 256) ? q1b1[j] : q2b1[j - 256];
    } else if (idx < 156544) {
        int i2 = idx - 140160;
        g_W1b[i2] = to_tf32(g1w2[i2]);
    } else if (idx < 222080) {
        int i2 = idx - 156544;
        g_QW2a[i2] = to_tf32(q1w2[i2]);
    } else if (idx < 287616) {
        int i2 = idx - 222080;
        g_QW2b[i2] = to_tf32(q2w2[i2]);
    }
}

// actterm[b][j] = sum_k action[b][k]*W1cat[96+k][j] + b1cat[j]  (raw weights, fp32)
__global__ void actterm_kernel(const float* __restrict__ action,
                               const float* __restrict__ g1w1,
                               const float* __restrict__ g1b1) {
    __shared__ float av[32];
    int b = blockIdx.x, j = threadIdx.x;
    if (j < 32) av[j] = action[b * 32 + j];
    __syncthreads();
    float acc = (j < 128) ? g1b1[j] : 0.f;
    const float* base = (j < 128) ? &g1w1[96 * 128 + j] : &g1w1[224 * 128 + (j - 128)];
    #pragma unroll 8
    for (int k = 0; k < 32; k++) acc = fmaf(av[k], base[k * 128], acc);
    g_actterm[b * 256 + j] = acc;
}

__global__ void xr_kernel(const float4* __restrict__ x4) {
    int i = blockIdx.x * blockDim.x + threadIdx.x;
    float4 v = x4[i];
    v.x = to_tf32(v.x); v.y = to_tf32(v.y);
    v.z = to_tf32(v.z); v.w = to_tf32(v.w);
    *(float4*)&g_xr[(size_t)i * 4] = v;
}

// ---------------- CSR build -----------------------------------------------------

__global__ void zero_kernel() {
    int idx = blockIdx.x * blockDim.x + threadIdx.x;
    if (idx < NN) g_deg[idx] = 0;
}

__global__ void count_kernel(const int4* __restrict__ dst4) {
    int i = blockIdx.x * blockDim.x + threadIdx.x;
    int4 d = dst4[i];
    atomicAdd(&g_deg[d.x], 1);
    atomicAdd(&g_deg[d.y], 1);
    atomicAdd(&g_deg[d.z], 1);
    atomicAdd(&g_deg[d.w], 1);
}

__global__ void blocksum_kernel() {
    __shared__ int sh[256];
    int t = threadIdx.x;
    sh[t] = g_deg[blockIdx.x * 256 + t];
    __syncthreads();
    for (int off = 128; off > 0; off >>= 1) {
        if (t < off) sh[t] += sh[t + off];
        __syncthreads();
    }
    if (t == 0) g_bsum[blockIdx.x] = sh[0];
}

__global__ void bscan_kernel() {
    __shared__ int sh[256];
    int t = threadIdx.x;
    sh[t] = g_bsum[t];
    __syncthreads();
    for (int off = 1; off < 256; off <<= 1) {
        int v = (t >= off) ? sh[t - off] : 0;
        __syncthreads();
        sh[t] += v;
        __syncthreads();
    }
    g_boff[t] = sh[t] - g_bsum[t];
}

__global__ void fill_kernel() {
    __shared__ int sh[256];
    int t = threadIdx.x;
    int gi = blockIdx.x * 256 + t;
    int d = g_deg[gi];
    sh[t] = d;
    __syncthreads();
    for (int off = 1; off < 256; off <<= 1) {
        int v = (t >= off) ? sh[t - off] : 0;
        __syncthreads();
        sh[t] += v;
        __syncthreads();
    }
    int excl = sh[t] - d + g_boff[blockIdx.x];
    g_off[gi] = excl;
    g_cur[gi] = excl;
}

__global__ void scatter_kernel(const int4* __restrict__ src4, const int4* __restrict__ dst4) {
    int i = blockIdx.x * blockDim.x + threadIdx.x;
    int4 s = src4[i];
    int4 d = dst4[i];
    g_csr[atomicAdd(&g_cur[d.x], 1)] = s.x;
    g_csr[atomicAdd(&g_cur[d.y], 1)] = s.y;
    g_csr[atomicAdd(&g_cur[d.z], 1)] = s.z;
    g_csr[atomicAdd(&g_cur[d.w], 1)] = s.w;
}

// ---------------- tf32 GEMM (cp.async double-buffered; operands pre-rounded) --
__global__ void __launch_bounds__(256, 2)
gemm_db_kernel(const float* __restrict__ A, const float* __restrict__ W,
               const float* __restrict__ bias, float* __restrict__ C,
               int K, int Nc, int lda, int do_relu, int do_round,
               const float* __restrict__ rowadd,
               const float* Wb, const float* biasb, float* Cb, int acoloff) {
    if (blockIdx.z == 1) {
        A += acoloff;
        W = Wb;
        bias = biasb;
        C = Cb;
    }
    extern __shared__ float sm[];
    float* AsB = sm;
    float* BsB = sm + 2 * 128 * 36;
    const int ASZ = 128 * 36, BSZ = 32 * 136;
    int bm = blockIdx.y * 128;
    int bn = blockIdx.x * 128;
    int t = threadIdx.x;
    int warp = t >> 5, lane = t & 31;
    int wm = warp >> 2, wn = warp & 3;
    int gid = lane >> 2, tig = lane & 3;

    int ar[4], ak[4], bk[4], bn4[4];
    #pragma unroll
    for (int i = 0; i < 4; i++) {
        int idx = t + i * 256;
        ar[i] = idx >> 3;  ak[i]  = (idx & 7) << 2;
        bk[i] = idx >> 5;  bn4[i] = (idx & 31) << 2;
    }

    float acc[4][4][4];
    #pragma unroll
    for (int a = 0; a < 4; a++)
        #pragma unroll
        for (int b = 0; b < 4; b++)
            #pragma unroll
            for (int c = 0; c < 4; c++) acc[a][b][c] = 0.f;

    int ntiles = K >> 5;
    #pragma unroll
    for (int i = 0; i < 4; i++)
        cp16((uint32_t)__cvta_generic_to_shared(&AsB[ar[i] * 36 + ak[i]]),
             &A[(size_t)(bm + ar[i]) * lda + ak[i]]);
    #pragma unroll
    for (int i = 0; i < 4; i++)
        cp16((uint32_t)__cvta_generic_to_shared(&BsB[bk[i] * 136 + bn4[i]]),
             &W[(size_t)bk[i] * Nc + bn + bn4[i]]);
    asm volatile("cp.async.commit_group;" ::: "memory");

    for (int it = 0; it < ntiles; it++) {
        if (it + 1 < ntiles) {
            int st = (it + 1) & 1;
            int k0 = (it + 1) * 32;
            #pragma unroll
            for (int i = 0; i < 4; i++)
                cp16((uint32_t)__cvta_generic_to_shared(&AsB[st * ASZ + ar[i] * 36 + ak[i]]),
                     &A[(size_t)(bm + ar[i]) * lda + k0 + ak[i]]);
            #pragma unroll
            for (int i = 0; i < 4; i++)
                cp16((uint32_t)__cvta_generic_to_shared(&BsB[st * BSZ + bk[i] * 136 + bn4[i]]),
                     &W[(size_t)(k0 + bk[i]) * Nc + bn + bn4[i]]);
            asm volatile("cp.async.commit_group;" ::: "memory");
            asm volatile("cp.async.wait_group 1;" ::: "memory");
        } else {
            asm volatile("cp.async.wait_group 0;" ::: "memory");
        }
        __syncthreads();
        const float* as = &AsB[(it & 1) * ASZ];
        const float* bs = &BsB[(it & 1) * BSZ];
        #pragma unroll
        for (int ks = 0; ks < 32; ks += 8) {
            uint32_t af[4][4], bf[4][2];
            #pragma unroll
            for (int mt = 0; mt < 4; mt++) {
                const float* ap = &as[(wm * 64 + mt * 16 + gid) * 36 + ks + tig];
                af[mt][0] = __float_as_uint(ap[0]);
                af[mt][1] = __float_as_uint(ap[8 * 36]);
                af[mt][2] = __float_as_uint(ap[4]);
                af[mt][3] = __float_as_uint(ap[8 * 36 + 4]);
            }
            #pragma unroll
            for (int nt = 0; nt < 4; nt++) {
                const float* bp = &bs[(ks + tig) * 136 + wn * 32 + nt * 8 + gid];
                bf[nt][0] = __float_as_uint(bp[0]);
                bf[nt][1] = __float_as_uint(bp[4 * 136]);
            }
            #pragma unroll
            for (int mt = 0; mt < 4; mt++)
                #pragma unroll
                for (int nt = 0; nt < 4; nt++) MMA_TF32(acc[mt][nt], af[mt], bf[nt]);
        }
        __syncthreads();
    }

    #pragma unroll
    for (int mt = 0; mt < 4; mt++) {
        int r0 = bm + wm * 64 + mt * 16 + gid;
        int r1 = r0 + 8;
        #pragma unroll
        for (int nt = 0; nt < 4; nt++) {
            int c0 = bn + wn * 32 + nt * 8 + 2 * tig;
            float b0 = bias ? bias[c0] : 0.f;
            float b1 = bias ? bias[c0 + 1] : 0.f;
            float ra00 = 0.f, ra01 = 0.f, ra10 = 0.f, ra11 = 0.f;
            if (rowadd) {
                ra00 = rowadd[(size_t)(r0 >> 6) * Nc + c0];
                ra01 = rowadd[(size_t)(r0 >> 6) * Nc + c0 + 1];
                ra10 = rowadd[(size_t)(r1 >> 6) * Nc + c0];
                ra11 = rowadd[(size_t)(r1 >> 6) * Nc + c0 + 1];
            }
            float v00 = acc[mt][nt][0] + b0 + ra00;
            float v01 = acc[mt][nt][1] + b1 + ra01;
            float v10 = acc[mt][nt][2] + b0 + ra10;
            float v11 = acc[mt][nt][3] + b1 + ra11;
            if (do_relu) {
                v00 = fmaxf(v00, 0.f); v01 = fmaxf(v01, 0.f);
                v10 = fmaxf(v10, 0.f); v11 = fmaxf(v11, 0.f);
            }
            if (do_round) {
                v00 = to_tf32(v00); v01 = to_tf32(v01);
                v10 = to_tf32(v10); v11 = to_tf32(v11);
            }
            float2 o0 = {v00, v01};
            float2 o1 = {v10, v11};
            *(float2*)&C[(size_t)r0 * Nc + c0] = o0;
            *(float2*)&C[(size_t)r1 * Nc + c0] = o1;
        }
    }
}

// ---------------- gnn_mid: agg1 + h1-GEMM + AB2-GEMM fused --------------------
// grid 512 blocks (128 nodes each). smem: S[128*132] tile + Bs[32*136].
__device__ __forceinline__ void acc_relu4(float4& acc, float4 a, float4 b) {
    acc.x += fmaxf(a.x + b.x, 0.f);
    acc.y += fmaxf(a.y + b.y, 0.f);
    acc.z += fmaxf(a.z + b.z, 0.f);
    acc.w += fmaxf(a.w + b.w, 0.f);
}

__global__ void __launch_bounds__(256, 2)
gnn_mid_kernel(const float* __restrict__ W1b, const float* __restrict__ b1b,
               const float* __restrict__ W2c, const float* __restrict__ b2c) {
    extern __shared__ float sm[];
    float* S  = sm;                 // 128*132: sum1 tile, then h1 tile
    float* Bs = sm + 128 * 132;     // 32*136
    int bm = blockIdx.x * 128;
    int t = threadIdx.x;
    int warp = t >> 5, lane = t & 31;
    int wm = warp >> 2, wn = warp & 3;
    int gid = lane >> 2, tig = lane & 3;

    // ---- phase A: aggregate 16 nodes per warp into S (tf32-rounded means) ----
    for (int ii = 0; ii < 16; ii++) {
        int r = warp * 16 + ii;
        int node = bm + r;
        int deg = g_deg[node], start = g_off[node];
        float4 a = *(const float4*)&g_AB1[(size_t)node * 256 + lane * 4];
        float4 acc = {0.f, 0.f, 0.f, 0.f};
        int i = 0;
        for (; i + 8 <= deg; i += 8) {
            int s[8];
            #pragma unroll
            for (int u = 0; u < 8; u++) s[u] = g_csr[start + i + u];
            float4 b[8];
            #pragma unroll
            for (int u = 0; u < 8; u++)
                b[u] = *(const float4*)&g_AB1[(size_t)s[u] * 256 + 128 + lane * 4];
            #pragma unroll
            for (int u = 0; u < 8; u++) acc_relu4(acc, a, b[u]);
        }
        for (; i + 2 <= deg; i += 2) {
            int s0 = g_csr[start + i], s1 = g_csr[start + i + 1];
            float4 b0 = *(const float4*)&g_AB1[(size_t)s0 * 256 + 128 + lane * 4];
            float4 b1 = *(const float4*)&g_AB1[(size_t)s1 * 256 + 128 + lane * 4];
            acc_relu4(acc, a, b0);
            acc_relu4(acc, a, b1);
        }
        for (; i < deg; i++) {
            int s = g_csr[start + i];
            float4 b = *(const float4*)&g_AB1[(size_t)s * 256 + 128 + lane * 4];
            acc_relu4(acc, a, b);
        }
        float inv = 1.f / fmaxf((float)deg, 1.f);
        float2 o0 = {to_tf32(acc.x * inv), to_tf32(acc.y * inv)};
        float2 o1 = {to_tf32(acc.z * inv), to_tf32(acc.w * inv)};
        *(float2*)&S[r * 132 + lane * 4] = o0;
        *(float2*)&S[r * 132 + lane * 4 + 2] = o1;
    }
    __syncthreads();

    // ---- phase B: acc = S @ W1b (K=128, Nc=128) ----
    int bk[4], bn4[4];
    #pragma unroll
    for (int i = 0; i < 4; i++) {
        int idx = t + i * 256;
        bk[i] = idx >> 5;  bn4[i] = (idx & 31) << 2;
    }
    float acc[4][4][4];
    #pragma unroll
    for (int a = 0; a < 4; a++)
        #pragma unroll
        for (int b = 0; b < 4; b++)
            #pragma unroll
            for (int c = 0; c < 4; c++) acc[a][b][c] = 0.f;

    float4 rb[4];
    #pragma unroll
    for (int i = 0; i < 4; i++)
        rb[i] = *(const float4*)&W1b[(size_t)bk[i] * 128 + bn4[i]];
    for (int k0 = 0; k0 < 128; k0 += 32) {
        #pragma unroll
        for (int i = 0; i < 4; i++)
            *(float4*)&Bs[bk[i] * 136 + bn4[i]] = rb[i];
        __syncthreads();
        if (k0 + 32 < 128) {
            #pragma unroll
            for (int i = 0; i < 4; i++)
                rb[i] = *(const float4*)&W1b[(size_t)(k0 + 32 + bk[i]) * 128 + bn4[i]];
        }
        #pragma unroll
        for (int ks = 0; ks < 32; ks += 8) {
            uint32_t af[4][4], bf[4][2];
            #pragma unroll
            for (int mt = 0; mt < 4; mt++) {
                const float* ap = &S[(wm * 64 + mt * 16 + gid) * 132 + k0 + ks + tig];
                af[mt][0] = __float_as_uint(ap[0]);
                af[mt][1] = __float_as_uint(ap[8 * 132]);
                af[mt][2] = __float_as_uint(ap[4]);
                af[mt][3] = __float_as_uint(ap[8 * 132 + 4]);
            }
            #pragma unroll
            for (int nt = 0; nt < 4; nt++) {
                const float* bp = &Bs[(ks + tig) * 136 + wn * 32 + nt * 8 + gid];
                bf[nt][0] = __float_as_uint(bp[0]);
                bf[nt][1] = __float_as_uint(bp[4 * 136]);
            }
            #pragma unroll
            for (int mt = 0; mt < 4; mt++)
                #pragma unroll
                for (int nt = 0; nt < 4; nt++) MMA_TF32(acc[mt][nt], af[mt], bf[nt]);
        }
        __syncthreads();
    }

    // ---- phase B epilogue: h1 -> S (relu, mask, tf32) ----
    #pragma unroll
    for (int mt = 0; mt < 4; mt++) {
        int rl0 = wm * 64 + mt * 16 + gid;
        int rl1 = rl0 + 8;
        float zm0 = (g_deg[bm + rl0] == 0) ? 0.f : 1.f;
        float zm1 = (g_deg[bm + rl1] == 0) ? 0.f : 1.f;
        #pragma unroll
        for (int nt = 0; nt < 4; nt++) {
            int c0 = wn * 32 + nt * 8 + 2 * tig;
            float b0 = b1b[c0], b1 = b1b[c0 + 1];
            float2 o0 = {to_tf32(fmaxf(acc[mt][nt][0] + b0, 0.f) * zm0),
                         to_tf32(fmaxf(acc[mt][nt][1] + b1, 0.f) * zm0)};
            float2 o1 = {to_tf32(fmaxf(acc[mt][nt][2] + b0, 0.f) * zm1),
                         to_tf32(fmaxf(acc[mt][nt][3] + b1, 0.f) * zm1)};
            *(float2*)&S[rl0 * 132 + c0] = o0;
            *(float2*)&S[rl1 * 132 + c0] = o1;
            acc[mt][nt][0] = 0.f; acc[mt][nt][1] = 0.f;
            acc[mt][nt][2] = 0.f; acc[mt][nt][3] = 0.f;
        }
    }
    __syncthreads();

    // ---- phase C: AB2 = S(h1) @ W2cat ----
    #pragma unroll
    for (int i = 0; i < 4; i++)
        rb[i] = *(const float4*)&W2c[(size_t)bk[i] * 128 + bn4[i]];
    for (int k0 = 0; k0 < 128; k0 += 32) {
        #pragma unroll
        for (int i = 0; i < 4; i++)
            *(float4*)&Bs[bk[i] * 136 + bn4[i]] = rb[i];
        __syncthreads();
        if (k0 + 32 < 128) {
            #pragma unroll
            for (int i = 0; i < 4; i++)
                rb[i] = *(const float4*)&W2c[(size_t)(k0 + 32 + bk[i]) * 128 + bn4[i]];
        }
        #pragma unroll
        for (int ks = 0; ks < 32; ks += 8) {
            uint32_t af[4][4], bf[4][2];
            #pragma unroll
            for (int mt = 0; mt < 4; mt++) {
                const float* ap = &S[(wm * 64 + mt * 16 + gid) * 132 + k0 + ks + tig];
                af[mt][0] = __float_as_uint(ap[0]);
                af[mt][1] = __float_as_uint(ap[8 * 132]);
                af[mt][2] = __float_as_uint(ap[4]);
                af[mt][3] = __float_as_uint(ap[8 * 132 + 4]);
            }
            #pragma unroll
            for (int nt = 0; nt < 4; nt++) {
                const float* bp = &Bs[(ks + tig) * 136 + wn * 32 + nt * 8 + gid];
                bf[nt][0] = __float_as_uint(bp[0]);
                bf[nt][1] = __float_as_uint(bp[4 * 136]);
            }
            #pragma unroll
            for (int mt = 0; mt < 4; mt++)
                #pragma unroll
                for (int nt = 0; nt < 4; nt++) MMA_TF32(acc[mt][nt], af[mt], bf[nt]);
        }
        __syncthreads();
    }

    #pragma unroll
    for (int mt = 0; mt < 4; mt++) {
        int r0 = bm + wm * 64 + mt * 16 + gid;
        int r1 = r0 + 8;
        #pragma unroll
        for (int nt = 0; nt < 4; nt++) {
            int c0 = wn * 32 + nt * 8 + 2 * tig;
            float b0 = b2c[c0], b1 = b2c[c0 + 1];
            float2 o0 = {acc[mt][nt][0] + b0, acc[mt][nt][1] + b1};
            float2 o1 = {acc[mt][nt][2] + b0, acc[mt][nt][3] + b1};
            *(float2*)&g_AB2[(size_t)r0 * 128 + c0] = o0;
            *(float2*)&g_AB2[(size_t)r1 * 128 + c0] = o1;
        }
    }
}

// ---------------- gnn_tail: agg2 + graph reduce + z build ---------------------
__device__ __forceinline__ void acc_relu2(float2& acc, float2 a, float2 b) {
    acc.x += fmaxf(a.x + b.x, 0.f);
    acc.y += fmaxf(a.y + b.y, 0.f);
}

__global__ void gnn_tail_kernel(const float* __restrict__ state,
                                const float* __restrict__ action,
                                const float* __restrict__ w2,
                                const float* __restrict__ b2) {
    __shared__ float P[8][64];
    __shared__ float S2[64];
    __shared__ int npw[8];
    int g = blockIdx.x;
    int t = threadIdx.x;
    int w = t >> 5, lane = t & 31;

    float2 accg = {0.f, 0.f};
    int cnt = 0;
    for (int ii = 0; ii < 8; ii++) {
        int node = g * 64 + w * 8 + ii;
        int deg = g_deg[node], start = g_off[node];
        float2 a = *(const float2*)&g_AB2[(size_t)node * 128 + lane * 2];
        float2 acc = {0.f, 0.f};
        int i = 0;
        for (; i + 8 <= deg; i += 8) {
            int s[8];
            #pragma unroll
            for (int u = 0; u < 8; u++) s[u] = g_csr[start + i + u];
            float2 b[8];
            #pragma unroll
            for (int u = 0; u < 8; u++)
                b[u] = *(const float2*)&g_AB2[(size_t)s[u] * 128 + 64 + lane * 2];
            #pragma unroll
            for (int u = 0; u < 8; u++) acc_relu2(acc, a, b[u]);
        }
        for (; i + 2 <= deg; i += 2) {
            int s0 = g_csr[start + i], s1 = g_csr[start + i + 1];
            float2 b0 = *(const float2*)&g_AB2[(size_t)s0 * 128 + 64 + lane * 2];
            float2 b1 = *(const float2*)&g_AB2[(size_t)s1 * 128 + 64 + lane * 2];
            acc_relu2(acc, a, b0);
            acc_relu2(acc, a, b1);
        }
        for (; i < deg; i++) {
            int s = g_csr[start + i];
            float2 b = *(const float2*)&g_AB2[(size_t)s * 128 + 64 + lane * 2];
            acc_relu2(acc, a, b);
        }
        if (deg > 0) {
            float inv = 1.f / (float)deg;
            accg.x += acc.x * inv;
            accg.y += acc.y * inv;
            cnt++;
        }
    }
    P[w][lane * 2] = accg.x;
    P[w][lane * 2 + 1] = accg.y;
    if (lane == 0) npw[w] = cnt;
    __syncthreads();
    if (t < 64) {
        float s = 0.f;
        #pragma unroll
        for (int u = 0; u < 8; u++) s += P[u][t];
        S2[t] = s;
    }
    __syncthreads();
    if (t < 64) {
        float npos = (float)(npw[0] + npw[1] + npw[2] + npw[3] +
                             npw[4] + npw[5] + npw[6] + npw[7]);
        float acc = 0.f;
        #pragma unroll 8
        for (int k = 0; k < 64; k++) acc = fmaf(S2[k], w2[k * 64 + t], acc);
        g_z[g * 192 + 128 + t] = to_tf32((acc + npos * b2[t]) * (1.f / 64.f));
    } else if (t < 192) {
        int j = t - 64;
        float v = (j < 96) ? state[g * 96 + j] : action[g * 32 + (j - 96)];
        g_z[g * 192 + j] = to_tf32(v);
    }
}

__global__ void qdot_kernel(const float* __restrict__ w3a, const float* __restrict__ b3a,
                            const float* __restrict__ w3b, const float* __restrict__ b3b,
                            float* __restrict__ out) {
    int warp = (blockIdx.x * blockDim.x + threadIdx.x) >> 5;
    int lane = threadIdx.x & 31;
    if (warp >= 2 * NB) return;
    int head = warp >> 10;
    const float* w3 = head ? w3b : w3a;
    const float* b3 = head ? b3b : b3a;
    const float* t2 = &g_t2[(size_t)warp * 256];
    float s = 0.f;
    #pragma unroll
    for (int k = lane; k < 256; k += 32) s += t2[k] * w3[k];
    #pragma unroll
    for (int o = 16; o > 0; o >>= 1) s += __shfl_down_sync(0xffffffffu, s, o);
    if (lane == 0) out[warp] = s + b3[0];
}

// ---------------- launch ------------------------------------------------------

extern "C" void kernel_launch(void* const* d_in, const int* in_sizes, int n_in,
                              void* d_out, int out_size) {
    const float* state  = (const float*)d_in[0];
    const float* action = (const float*)d_in[1];
    const float* x      = (const float*)d_in[2];
    const int*   eidx   = (const int*)d_in[3];
    const float* g1_w1 = (const float*)d_in[5];
    const float* g1_b1 = (const float*)d_in[6];
    const float* g1_w2 = (const float*)d_in[7];
    const float* g1_b2 = (const float*)d_in[8];
    const float* g2_w1 = (const float*)d_in[9];
    const float* g2_b1 = (const float*)d_in[10];
    const float* g2_w2 = (const float*)d_in[11];
    const float* g2_b2 = (const float*)d_in[12];
    const float* q1_w1 = (const float*)d_in[13];
    const float* q1_b1 = (const float*)d_in[14];
    const float* q1_w2 = (const float*)d_in[15];
    const float* q1_b2 = (const float*)d_in[16];
    const float* q1_w3 = (const float*)d_in[17];
    const float* q1_b3 = (const float*)d_in[18];
    const float* q2_w1 = (const float*)d_in[19];
    const float* q2_b1 = (const float*)d_in[20];
    const float* q2_w2 = (const float*)d_in[21];
    const float* q2_b2 = (const float*)d_in[22];
    const float* q2_w3 = (const float*)d_in[23];
    const float* q2_b3 = (const float*)d_in[24];
    float* out = (float*)d_out;

    const int4* srcs4 = (const int4*)eidx;
    const int4* dsts4 = (const int4*)(eidx + NE);

    float *p_xr, *p_AB1, *p_z, *p_t1, *p_t2;
    float *p_W1, *p_b1, *p_W2, *p_b2, *p_W1b, *p_act, *p_QW1, *p_Qb1, *p_QW2a, *p_QW2b;
    cudaGetSymbolAddress((void**)&p_xr,   g_xr);
    cudaGetSymbolAddress((void**)&p_AB1,  g_AB1);
    cudaGetSymbolAddress((void**)&p_z,    g_z);
    cudaGetSymbolAddress((void**)&p_t1,   g_t1);
    cudaGetSymbolAddress((void**)&p_t2,   g_t2);
    cudaGetSymbolAddress((void**)&p_W1,   g_W1);
    cudaGetSymbolAddress((void**)&p_b1,   g_bias1);
    cudaGetSymbolAddress((void**)&p_W2,   g_W2);
    cudaGetSymbolAddress((void**)&p_b2,   g_bias2);
    cudaGetSymbolAddress((void**)&p_W1b,  g_W1b);
    cudaGetSymbolAddress((void**)&p_act,  g_actterm);
    cudaGetSymbolAddress((void**)&p_QW1,  g_QW1);
    cudaGetSymbolAddress((void**)&p_Qb1,  g_Qb1);
    cudaGetSymbolAddress((void**)&p_QW2a, g_QW2a);
    cudaGetSymbolAddress((void**)&p_QW2b, g_QW2b);

    const int GEMM_SMEM = (2 * 128 * 36 + 2 * 32 * 136) * 4;      // 71680
    const int MID_SMEM  = (128 * 132 + 32 * 136) * 4;             // 84992
    cudaFuncSetAttribute(gemm_db_kernel, cudaFuncAttributeMaxDynamicSharedMemorySize, GEMM_SMEM);
    cudaFuncSetAttribute(gnn_mid_kernel, cudaFuncAttributeMaxDynamicSharedMemorySize, MID_SMEM);

    cudaStream_t s2;
    cudaEvent_t eFork, eA, eJoin;
    cudaStreamCreateWithFlags(&s2, cudaStreamNonBlocking);
    cudaEventCreateWithFlags(&eFork, cudaEventDisableTiming);
    cudaEventCreateWithFlags(&eA, cudaEventDisableTiming);
    cudaEventCreateWithFlags(&eJoin, cudaEventDisableTiming);

    cudaEventRecord(eFork, 0);
    cudaStreamWaitEvent(s2, eFork, 0);

    // ---- side stream: xr round, actterm (raw weights), CSR build ----
    xr_kernel<<<(NN * 96 / 4) / 256, 256, 0, s2>>>((const float4*)x);
    actterm_kernel<<<NB, 256, 0, s2>>>(action, g1_w1, g1_b1);
    cudaEventRecord(eA, s2);
    zero_kernel<<<NN / 256, 256, 0, s2>>>();
    count_kernel<<<NE / 4 / 256, 256, 0, s2>>>(dsts4);
    blocksum_kernel<<<256, 256, 0, s2>>>();
    bscan_kernel<<<1, 256, 0, s2>>>();
    fill_kernel<<<256, 256, 0, s2>>>();
    scatter_kernel<<<NE / 4 / 256, 256, 0, s2>>>(srcs4, dsts4);
    cudaEventRecord(eJoin, s2);

    // ---- main stream ----
    prep_kernel<<<(287616 + 255) / 256, 256>>>(g1_w1, g1_b1, g1_w2, g2_w1, g2_b1,
                                               q1_w1, q1_b1, q1_w2, q2_w1, q2_b1, q2_w2);
    cudaStreamWaitEvent(0, eA, 0);
    gemm_db_kernel<<<dim3(2, NN / 128), 256, GEMM_SMEM>>>(
        p_xr, p_W1, nullptr, p_AB1, 96, 256, 96, 0, 0, p_act,
        nullptr, nullptr, nullptr, 0);
    cudaStreamWaitEvent(0, eJoin, 0);
    gnn_mid_kernel<<<NN / 128, 256, MID_SMEM>>>(p_W1b, g1_b2, p_W2, p_b2);
    gnn_tail_kernel<<<NB, 256>>>(state, action, g2_w2, g2_b2);
    gemm_db_kernel<<<dim3(4, NB / 128), 256, GEMM_SMEM>>>(
        p_z, p_QW1, p_Qb1, p_t1, 192, 512, 192, 1, 1, nullptr,
        nullptr, nullptr, nullptr, 0);
    gemm_db_kernel<<<dim3(2, NB / 128, 2), 256, GEMM_SMEM>>>(
        p_t1, p_QW2a, q1_b2, p_t2, 256, 256, 512, 1, 0, nullptr,
        p_QW2b, q2_b2, p_t2 + NB * 256, 256);
    qdot_kernel<<<(2 * NB * 32) / 256, 256>>>(q1_w3, q1_b3, q2_w3, q2_b3, out);
}

// round 11
// speedup vs baseline: 1.0487x; 1.0487x over previous
#include <cuda_runtime.h>
#include <cstdint>

#define NN 65536
#define NE 524288
#define NB 1024

// ---------------- scratch (device globals) ----------------------------------
__device__ float g_xr[NN * 96];     // tf32-rounded x
__device__ float g_AB1[NN * 256];
__device__ float g_sum1[NN * 128];  // tf32-rounded means
__device__ float g_h1[NN * 128];    // tf32-rounded h1
__device__ float g_AB2[NN * 128];
__device__ float g_z[NB * 192];     // tf32-rounded z
__device__ float g_t1[NB * 512];    // tf32-rounded t1
__device__ float g_t2[2 * NB * 256];
__device__ float g_actterm[NB * 256];
__device__ float g_W1[96 * 256];    // tf32-rounded x-path rows
__device__ float g_W2[128 * 128];   // tf32-rounded W2cat
__device__ float g_bias2[128];
__device__ float g_W1b[128 * 128];  // tf32(g1_w2)
__device__ float g_QW1[192 * 512];  // tf32-rounded
__device__ float g_Qb1[512];
__device__ float g_QW2a[256 * 256]; // tf32(q1_w2)
__device__ float g_QW2b[256 * 256]; // tf32(q2_w2)
__device__ int   g_deg[NN];
__device__ int   g_off[NN];
__device__ int   g_cur[NN];
__device__ int   g_csr[NE];
__device__ int   g_bsum[256];
__device__ int   g_boff[256];

// ---------------- tf32 helpers -------------------------------------------------

__device__ __forceinline__ float to_tf32(float x) {
    uint32_t u;
    asm("cvt.rna.tf32.f32 %0, %1;" : "=r"(u) : "f"(x));
    return __uint_as_float(u);
}

#define MMA_TF32(acc, af, bf)                                              \
    asm volatile(                                                          \
        "mma.sync.aligned.m16n8k8.row.col.f32.tf32.tf32.f32 "              \
        "{%0,%1,%2,%3}, {%4,%5,%6,%7}, {%8,%9}, {%0,%1,%2,%3};"            \
        : "+f"(acc[0]), "+f"(acc[1]), "+f"(acc[2]), "+f"(acc[3])           \
        : "r"(af[0]), "r"(af[1]), "r"(af[2]), "r"(af[3]),                  \
          "r"(bf[0]), "r"(bf[1]))

__device__ __forceinline__ void cp16(uint32_t s, const void* g) {
    asm volatile("cp.async.ca.shared.global [%0], [%1], 16;" :: "r"(s), "l"(g));
}

// ---------------- prep: pack + tf32-round GEMM weights ------------------------

__global__ void prep_kernel(const float* __restrict__ g1w1,
                            const float* __restrict__ g1w2,
                            const float* __restrict__ g2w1, const float* __restrict__ g2b1,
                            const float* __restrict__ q1w1, const float* __restrict__ q1b1,
                            const float* __restrict__ q1w2,
                            const float* __restrict__ q2w1, const float* __restrict__ q2b1,
                            const float* __restrict__ q2w2) {
    int idx = blockIdx.x * blockDim.x + threadIdx.x;
    if (idx < 24576) {   // W1 rows 0..95 (x path), tf32
        int k = idx >> 8, j = idx & 255;
        float v = (j < 128) ? g1w1[k * 128 + j] : g1w1[(k + 128) * 128 + (j - 128)];
        g_W1[idx] = to_tf32(v);
    } else if (idx < 40960) {
        int i2 = idx - 24576;
        int k = i2 >> 7, j = i2 & 127;
        float v = (j < 64) ? g2w1[k * 64 + j] : g2w1[(k + 128) * 64 + (j - 64)];
        g_W2[i2] = to_tf32(v);
    } else if (idx < 41088) {
        int j = idx - 40960;
        g_bias2[j] = (j < 64) ? g2b1[j] : 0.f;
    } else if (idx < 139392) {
        int i2 = idx - 41088;
        int k = i2 / 512, c = i2 & 511;
        float v = (c < 256) ? q1w1[k * 256 + c] : q2w1[k * 256 + (c - 256)];
        g_QW1[i2] = to_tf32(v);
    } else if (idx < 139904) {
        int j = idx - 139392;
        g_Qb1[j] = (j < 256) ? q1b1[j] : q2b1[j - 256];
    } else if (idx < 156288) {
        int i2 = idx - 139904;
        g_W1b[i2] = to_tf32(g1w2[i2]);
    } else if (idx < 221824) {
        int i2 = idx - 156288;
        g_QW2a[i2] = to_tf32(q1w2[i2]);
    } else if (idx < 287360) {
        int i2 = idx - 221824;
        g_QW2b[i2] = to_tf32(q2w2[i2]);
    }
}

// actterm[b][j] = sum_k action[b][k]*W1cat[96+k][j] + b1cat[j]  (raw weights)
__global__ void actterm_kernel(const float* __restrict__ action,
                               const float* __restrict__ g1w1,
                               const float* __restrict__ g1b1) {
    __shared__ float av[32];
    int b = blockIdx.x, j = threadIdx.x;
    if (j < 32) av[j] = action[b * 32 + j];
    __syncthreads();
    float acc = (j < 128) ? g1b1[j] : 0.f;
    const float* base = (j < 128) ? &g1w1[96 * 128 + j] : &g1w1[224 * 128 + (j - 128)];
    #pragma unroll 8
    for (int k = 0; k < 32; k++) acc = fmaf(av[k], base[k * 128], acc);
    g_actterm[b * 256 + j] = acc;
}

__global__ void xr_kernel(const float4* __restrict__ x4) {
    int i = blockIdx.x * blockDim.x + threadIdx.x;
    float4 v = x4[i];
    v.x = to_tf32(v.x); v.y = to_tf32(v.y);
    v.z = to_tf32(v.z); v.w = to_tf32(v.w);
    *(float4*)&g_xr[(size_t)i * 4] = v;
}

// ---------------- CSR build -----------------------------------------------------

__global__ void zero_kernel() {
    int idx = blockIdx.x * blockDim.x + threadIdx.x;
    if (idx < NN) g_deg[idx] = 0;
}

__global__ void count_kernel(const int4* __restrict__ dst4) {
    int i = blockIdx.x * blockDim.x + threadIdx.x;
    int4 d = dst4[i];
    atomicAdd(&g_deg[d.x], 1);
    atomicAdd(&g_deg[d.y], 1);
    atomicAdd(&g_deg[d.z], 1);
    atomicAdd(&g_deg[d.w], 1);
}

__global__ void blocksum_kernel() {
    __shared__ int sh[256];
    int t = threadIdx.x;
    sh[t] = g_deg[blockIdx.x * 256 + t];
    __syncthreads();
    for (int off = 128; off > 0; off >>= 1) {
        if (t < off) sh[t] += sh[t + off];
        __syncthreads();
    }
    if (t == 0) g_bsum[blockIdx.x] = sh[0];
}

__global__ void bscan_kernel() {
    __shared__ int sh[256];
    int t = threadIdx.x;
    sh[t] = g_bsum[t];
    __syncthreads();
    for (int off = 1; off < 256; off <<= 1) {
        int v = (t >= off) ? sh[t - off] : 0;
        __syncthreads();
        sh[t] += v;
        __syncthreads();
    }
    g_boff[t] = sh[t] - g_bsum[t];
}

__global__ void fill_kernel() {
    __shared__ int sh[256];
    int t = threadIdx.x;
    int gi = blockIdx.x * 256 + t;
    int d = g_deg[gi];
    sh[t] = d;
    __syncthreads();
    for (int off = 1; off < 256; off <<= 1) {
        int v = (t >= off) ? sh[t - off] : 0;
        __syncthreads();
        sh[t] += v;
        __syncthreads();
    }
    int excl = sh[t] - d + g_boff[blockIdx.x];
    g_off[gi] = excl;
    g_cur[gi] = excl;
}

__global__ void scatter_kernel(const int4* __restrict__ src4, const int4* __restrict__ dst4) {
    int i = blockIdx.x * blockDim.x + threadIdx.x;
    int4 s = src4[i];
    int4 d = dst4[i];
    g_csr[atomicAdd(&g_cur[d.x], 1)] = s.x;
    g_csr[atomicAdd(&g_cur[d.y], 1)] = s.y;
    g_csr[atomicAdd(&g_cur[d.z], 1)] = s.z;
    g_csr[atomicAdd(&g_cur[d.w], 1)] = s.w;
}

// ---------------- tf32 GEMM (cp.async double-buffered; operands pre-rounded) --
__global__ void __launch_bounds__(256, 2)
gemm_db_kernel(const float* __restrict__ A, const float* __restrict__ W,
               const float* __restrict__ bias, float* __restrict__ C,
               int K, int Nc, int lda, int do_relu, int do_round,
               const int* __restrict__ degmask,
               const float* __restrict__ rowadd,
               const float* Wb, const float* biasb, float* Cb, int acoloff) {
    if (blockIdx.z == 1) {
        A += acoloff;
        W = Wb;
        bias = biasb;
        C = Cb;
    }
    extern __shared__ float sm[];
    float* AsB = sm;
    float* BsB = sm + 2 * 128 * 36;
    const int ASZ = 128 * 36, BSZ = 32 * 136;
    int bm = blockIdx.y * 128;
    int bn = blockIdx.x * 128;
    int t = threadIdx.x;
    int warp = t >> 5, lane = t & 31;
    int wm = warp >> 2, wn = warp & 3;
    int gid = lane >> 2, tig = lane & 3;

    int ar[4], ak[4], bk[4], bn4[4];
    #pragma unroll
    for (int i = 0; i < 4; i++) {
        int idx = t + i * 256;
        ar[i] = idx >> 3;  ak[i]  = (idx & 7) << 2;
        bk[i] = idx >> 5;  bn4[i] = (idx & 31) << 2;
    }

    float acc[4][4][4];
    #pragma unroll
    for (int a = 0; a < 4; a++)
        #pragma unroll
        for (int b = 0; b < 4; b++)
            #pragma unroll
            for (int c = 0; c < 4; c++) acc[a][b][c] = 0.f;

    int ntiles = K >> 5;
    #pragma unroll
    for (int i = 0; i < 4; i++)
        cp16((uint32_t)__cvta_generic_to_shared(&AsB[ar[i] * 36 + ak[i]]),
             &A[(size_t)(bm + ar[i]) * lda + ak[i]]);
    #pragma unroll
    for (int i = 0; i < 4; i++)
        cp16((uint32_t)__cvta_generic_to_shared(&BsB[bk[i] * 136 + bn4[i]]),
             &W[(size_t)bk[i] * Nc + bn + bn4[i]]);
    asm volatile("cp.async.commit_group;" ::: "memory");

    for (int it = 0; it < ntiles; it++) {
        if (it + 1 < ntiles) {
            int st = (it + 1) & 1;
            int k0 = (it + 1) * 32;
            #pragma unroll
            for (int i = 0; i < 4; i++)
                cp16((uint32_t)__cvta_generic_to_shared(&AsB[st * ASZ + ar[i] * 36 + ak[i]]),
                     &A[(size_t)(bm + ar[i]) * lda + k0 + ak[i]]);
            #pragma unroll
            for (int i = 0; i < 4; i++)
                cp16((uint32_t)__cvta_generic_to_shared(&BsB[st * BSZ + bk[i] * 136 + bn4[i]]),
                     &W[(size_t)(k0 + bk[i]) * Nc + bn + bn4[i]]);
            asm volatile("cp.async.commit_group;" ::: "memory");
            asm volatile("cp.async.wait_group 1;" ::: "memory");
        } else {
            asm volatile("cp.async.wait_group 0;" ::: "memory");
        }
        __syncthreads();
        const float* as = &AsB[(it & 1) * ASZ];
        const float* bs = &BsB[(it & 1) * BSZ];
        #pragma unroll
        for (int ks = 0; ks < 32; ks += 8) {
            uint32_t af[4][4], bf[4][2];
            #pragma unroll
            for (int mt = 0; mt < 4; mt++) {
                const float* ap = &as[(wm * 64 + mt * 16 + gid) * 36 + ks + tig];
                af[mt][0] = __float_as_uint(ap[0]);
                af[mt][1] = __float_as_uint(ap[8 * 36]);
                af[mt][2] = __float_as_uint(ap[4]);
                af[mt][3] = __float_as_uint(ap[8 * 36 + 4]);
            }
            #pragma unroll
            for (int nt = 0; nt < 4; nt++) {
                const float* bp = &bs[(ks + tig) * 136 + wn * 32 + nt * 8 + gid];
                bf[nt][0] = __float_as_uint(bp[0]);
                bf[nt][1] = __float_as_uint(bp[4 * 136]);
            }
            #pragma unroll
            for (int mt = 0; mt < 4; mt++)
                #pragma unroll
                for (int nt = 0; nt < 4; nt++) MMA_TF32(acc[mt][nt], af[mt], bf[nt]);
        }
        __syncthreads();
    }

    #pragma unroll
    for (int mt = 0; mt < 4; mt++) {
        int r0 = bm + wm * 64 + mt * 16 + gid;
        int r1 = r0 + 8;
        float zm0 = (degmask && degmask[r0] == 0) ? 0.f : 1.f;
        float zm1 = (degmask && degmask[r1] == 0) ? 0.f : 1.f;
        #pragma unroll
        for (int nt = 0; nt < 4; nt++) {
            int c0 = bn + wn * 32 + nt * 8 + 2 * tig;
            float b0 = bias ? bias[c0] : 0.f;
            float b1 = bias ? bias[c0 + 1] : 0.f;
            float ra00 = 0.f, ra01 = 0.f, ra10 = 0.f, ra11 = 0.f;
            if (rowadd) {
                ra00 = rowadd[(size_t)(r0 >> 6) * Nc + c0];
                ra01 = rowadd[(size_t)(r0 >> 6) * Nc + c0 + 1];
                ra10 = rowadd[(size_t)(r1 >> 6) * Nc + c0];
                ra11 = rowadd[(size_t)(r1 >> 6) * Nc + c0 + 1];
            }
            float v00 = acc[mt][nt][0] + b0 + ra00;
            float v01 = acc[mt][nt][1] + b1 + ra01;
            float v10 = acc[mt][nt][2] + b0 + ra10;
            float v11 = acc[mt][nt][3] + b1 + ra11;
            if (do_relu) {
                v00 = fmaxf(v00, 0.f); v01 = fmaxf(v01, 0.f);
                v10 = fmaxf(v10, 0.f); v11 = fmaxf(v11, 0.f);
            }
            v00 *= zm0; v01 *= zm0; v10 *= zm1; v11 *= zm1;
            if (do_round) {
                v00 = to_tf32(v00); v01 = to_tf32(v01);
                v10 = to_tf32(v10); v11 = to_tf32(v11);
            }
            float2 o0 = {v00, v01};
            float2 o1 = {v10, v11};
            *(float2*)&C[(size_t)r0 * Nc + c0] = o0;
            *(float2*)&C[(size_t)r1 * Nc + c0] = o1;
        }
    }
}

// ---------------- edge aggregation (standalone, high occupancy) ---------------

__device__ __forceinline__ void acc_relu4(float4& acc, float4 a, float4 b) {
    acc.x += fmaxf(a.x + b.x, 0.f);
    acc.y += fmaxf(a.y + b.y, 0.f);
    acc.z += fmaxf(a.z + b.z, 0.f);
    acc.w += fmaxf(a.w + b.w, 0.f);
}

__global__ void agg1_kernel() {
    int w = (blockIdx.x * blockDim.x + threadIdx.x) >> 5;
    int lane = threadIdx.x & 31;
    int deg = g_deg[w], start = g_off[w];
    float4 a = *(const float4*)&g_AB1[(size_t)w * 256 + lane * 4];
    float4 acc = {0.f, 0.f, 0.f, 0.f};
    int i = 0;
    for (; i + 8 <= deg; i += 8) {
        int s[8];
        #pragma unroll
        for (int u = 0; u < 8; u++) s[u] = g_csr[start + i + u];
        float4 b[8];
        #pragma unroll
        for (int u = 0; u < 8; u++)
            b[u] = *(const float4*)&g_AB1[(size_t)s[u] * 256 + 128 + lane * 4];
        #pragma unroll
        for (int u = 0; u < 8; u++) acc_relu4(acc, a, b[u]);
    }
    for (; i + 2 <= deg; i += 2) {
        int s0 = g_csr[start + i], s1 = g_csr[start + i + 1];
        float4 b0 = *(const float4*)&g_AB1[(size_t)s0 * 256 + 128 + lane * 4];
        float4 b1 = *(const float4*)&g_AB1[(size_t)s1 * 256 + 128 + lane * 4];
        acc_relu4(acc, a, b0);
        acc_relu4(acc, a, b1);
    }
    for (; i < deg; i++) {
        int s = g_csr[start + i];
        float4 b = *(const float4*)&g_AB1[(size_t)s * 256 + 128 + lane * 4];
        acc_relu4(acc, a, b);
    }
    float inv = 1.f / fmaxf((float)deg, 1.f);
    float4 o = {to_tf32(acc.x * inv), to_tf32(acc.y * inv),
                to_tf32(acc.z * inv), to_tf32(acc.w * inv)};
    *(float4*)&g_sum1[(size_t)w * 128 + lane * 4] = o;
}

// ---------------- gnn_tail: agg2 + graph reduce + z build ---------------------
__device__ __forceinline__ void acc_relu2(float2& acc, float2 a, float2 b) {
    acc.x += fmaxf(a.x + b.x, 0.f);
    acc.y += fmaxf(a.y + b.y, 0.f);
}

__global__ void gnn_tail_kernel(const float* __restrict__ state,
                                const float* __restrict__ action,
                                const float* __restrict__ w2,
                                const float* __restrict__ b2) {
    __shared__ float P[8][64];
    __shared__ float S2[64];
    __shared__ int npw[8];
    int g = blockIdx.x;
    int t = threadIdx.x;
    int w = t >> 5, lane = t & 31;

    float2 accg = {0.f, 0.f};
    int cnt = 0;
    for (int ii = 0; ii < 8; ii++) {
        int node = g * 64 + w * 8 + ii;
        int deg = g_deg[node], start = g_off[node];
        float2 a = *(const float2*)&g_AB2[(size_t)node * 128 + lane * 2];
        float2 acc = {0.f, 0.f};
        int i = 0;
        for (; i + 8 <= deg; i += 8) {
            int s[8];
            #pragma unroll
            for (int u = 0; u < 8; u++) s[u] = g_csr[start + i + u];
            float2 b[8];
            #pragma unroll
            for (int u = 0; u < 8; u++)
                b[u] = *(const float2*)&g_AB2[(size_t)s[u] * 128 + 64 + lane * 2];
            #pragma unroll
            for (int u = 0; u < 8; u++) acc_relu2(acc, a, b[u]);
        }
        for (; i + 2 <= deg; i += 2) {
            int s0 = g_csr[start + i], s1 = g_csr[start + i + 1];
            float2 b0 = *(const float2*)&g_AB2[(size_t)s0 * 128 + 64 + lane * 2];
            float2 b1 = *(const float2*)&g_AB2[(size_t)s1 * 128 + 64 + lane * 2];
            acc_relu2(acc, a, b0);
            acc_relu2(acc, a, b1);
        }
        for (; i < deg; i++) {
            int s = g_csr[start + i];
            float2 b = *(const float2*)&g_AB2[(size_t)s * 128 + 64 + lane * 2];
            acc_relu2(acc, a, b);
        }
        if (deg > 0) {
            float inv = 1.f / (float)deg;
            accg.x += acc.x * inv;
            accg.y += acc.y * inv;
            cnt++;
        }
    }
    P[w][lane * 2] = accg.x;
    P[w][lane * 2 + 1] = accg.y;
    if (lane == 0) npw[w] = cnt;
    __syncthreads();
    if (t < 64) {
        float s = 0.f;
        #pragma unroll
        for (int u = 0; u < 8; u++) s += P[u][t];
        S2[t] = s;
    }
    __syncthreads();
    if (t < 64) {
        float npos = (float)(npw[0] + npw[1] + npw[2] + npw[3] +
                             npw[4] + npw[5] + npw[6] + npw[7]);
        float acc = 0.f;
        #pragma unroll 8
        for (int k = 0; k < 64; k++) acc = fmaf(S2[k], w2[k * 64 + t], acc);
        g_z[g * 192 + 128 + t] = to_tf32((acc + npos * b2[t]) * (1.f / 64.f));
    } else if (t < 192) {
        int j = t - 64;
        float v = (j < 96) ? state[g * 96 + j] : action[g * 32 + (j - 96)];
        g_z[g * 192 + j] = to_tf32(v);
    }
}

__global__ void qdot_kernel(const float* __restrict__ w3a, const float* __restrict__ b3a,
                            const float* __restrict__ w3b, const float* __restrict__ b3b,
                            float* __restrict__ out) {
    int warp = (blockIdx.x * blockDim.x + threadIdx.x) >> 5;
    int lane = threadIdx.x & 31;
    if (warp >= 2 * NB) return;
    int head = warp >> 10;
    const float* w3 = head ? w3b : w3a;
    const float* b3 = head ? b3b : b3a;
    const float* t2 = &g_t2[(size_t)warp * 256];
    float s = 0.f;
    #pragma unroll
    for (int k = lane; k < 256; k += 32) s += t2[k] * w3[k];
    #pragma unroll
    for (int o = 16; o > 0; o >>= 1) s += __shfl_down_sync(0xffffffffu, s, o);
    if (lane == 0) out[warp] = s + b3[0];
}

// ---------------- launch ------------------------------------------------------

extern "C" void kernel_launch(void* const* d_in, const int* in_sizes, int n_in,
                              void* d_out, int out_size) {
    const float* state  = (const float*)d_in[0];
    const float* action = (const float*)d_in[1];
    const float* x      = (const float*)d_in[2];
    const int*   eidx   = (const int*)d_in[3];
    const float* g1_w1 = (const float*)d_in[5];
    const float* g1_b1 = (const float*)d_in[6];
    const float* g1_w2 = (const float*)d_in[7];
    const float* g1_b2 = (const float*)d_in[8];
    const float* g2_w1 = (const float*)d_in[9];
    const float* g2_b1 = (const float*)d_in[10];
    const float* g2_w2 = (const float*)d_in[11];
    const float* g2_b2 = (const float*)d_in[12];
    const float* q1_w1 = (const float*)d_in[13];
    const float* q1_b1 = (const float*)d_in[14];
    const float* q1_w2 = (const float*)d_in[15];
    const float* q1_b2 = (const float*)d_in[16];
    const float* q1_w3 = (const float*)d_in[17];
    const float* q1_b3 = (const float*)d_in[18];
    const float* q2_w1 = (const float*)d_in[19];
    const float* q2_b1 = (const float*)d_in[20];
    const float* q2_w2 = (const float*)d_in[21];
    const float* q2_b2 = (const float*)d_in[22];
    const float* q2_w3 = (const float*)d_in[23];
    const float* q2_b3 = (const float*)d_in[24];
    float* out = (float*)d_out;

    const int4* srcs4 = (const int4*)eidx;
    const int4* dsts4 = (const int4*)(eidx + NE);

    float *p_xr, *p_AB1, *p_sum1, *p_h1, *p_AB2, *p_z, *p_t1, *p_t2;
    float *p_W1, *p_W2, *p_b2, *p_W1b, *p_act, *p_QW1, *p_Qb1, *p_QW2a, *p_QW2b;
    int *p_deg;
    cudaGetSymbolAddress((void**)&p_xr,   g_xr);
    cudaGetSymbolAddress((void**)&p_AB1,  g_AB1);
    cudaGetSymbolAddress((void**)&p_sum1, g_sum1);
    cudaGetSymbolAddress((void**)&p_h1,   g_h1);
    cudaGetSymbolAddress((void**)&p_AB2,  g_AB2);
    cudaGetSymbolAddress((void**)&p_z,    g_z);
    cudaGetSymbolAddress((void**)&p_t1,   g_t1);
    cudaGetSymbolAddress((void**)&p_t2,   g_t2);
    cudaGetSymbolAddress((void**)&p_W1,   g_W1);
    cudaGetSymbolAddress((void**)&p_W2,   g_W2);
    cudaGetSymbolAddress((void**)&p_b2,   g_bias2);
    cudaGetSymbolAddress((void**)&p_W1b,  g_W1b);
    cudaGetSymbolAddress((void**)&p_act,  g_actterm);
    cudaGetSymbolAddress((void**)&p_QW1,  g_QW1);
    cudaGetSymbolAddress((void**)&p_Qb1,  g_Qb1);
    cudaGetSymbolAddress((void**)&p_QW2a, g_QW2a);
    cudaGetSymbolAddress((void**)&p_QW2b, g_QW2b);
    cudaGetSymbolAddress((void**)&p_deg,  g_deg);

    const int GEMM_SMEM = (2 * 128 * 36 + 2 * 32 * 136) * 4;   // 71680 bytes
    cudaFuncSetAttribute(gemm_db_kernel, cudaFuncAttributeMaxDynamicSharedMemorySize, GEMM_SMEM);

    cudaStream_t s2;
    cudaEvent_t eFork, eA, eJoin;
    cudaStreamCreateWithFlags(&s2, cudaStreamNonBlocking);
    cudaEventCreateWithFlags(&eFork, cudaEventDisableTiming);
    cudaEventCreateWithFlags(&eA, cudaEventDisableTiming);
    cudaEventCreateWithFlags(&eJoin, cudaEventDisableTiming);

    cudaEventRecord(eFork, 0);
    cudaStreamWaitEvent(s2, eFork, 0);

    // ---- side stream: xr round + actterm + CSR build ----
    xr_kernel<<<(NN * 96 / 4) / 256, 256, 0, s2>>>((const float4*)x);
    actterm_kernel<<<NB, 256, 0, s2>>>(action, g1_w1, g1_b1);
    cudaEventRecord(eA, s2);
    zero_kernel<<<NN / 256, 256, 0, s2>>>();
    count_kernel<<<NE / 4 / 256, 256, 0, s2>>>(dsts4);
    blocksum_kernel<<<256, 256, 0, s2>>>();
    bscan_kernel<<<1, 256, 0, s2>>>();
    fill_kernel<<<256, 256, 0, s2>>>();
    scatter_kernel<<<NE / 4 / 256, 256, 0, s2>>>(srcs4, dsts4);
    cudaEventRecord(eJoin, s2);

    // ---- main stream ----
    prep_kernel<<<(287360 + 255) / 256, 256>>>(g1_w1, g1_w2, g2_w1, g2_b1,
                                               q1_w1, q1_b1, q1_w2, q2_w1, q2_b1, q2_w2);
    cudaStreamWaitEvent(0, eA, 0);
    // AB1 = xr @ W1[0:96] + actterm[graph]
    gemm_db_kernel<<<dim3(2, NN / 128), 256, GEMM_SMEM>>>(
        p_xr, p_W1, nullptr, p_AB1, 96, 256, 96, 0, 0, nullptr, p_act,
        nullptr, nullptr, nullptr, 0);
    cudaStreamWaitEvent(0, eJoin, 0);
    agg1_kernel<<<NN / 8, 256>>>();
    // h1 = round(relu(sum1 @ W1b + g1_b2) * mask)
    gemm_db_kernel<<<dim3(1, NN / 128), 256, GEMM_SMEM>>>(
        p_sum1, p_W1b, g1_b2, p_h1, 128, 128, 128, 1, 1, p_deg, nullptr,
        nullptr, nullptr, nullptr, 0);
    // AB2 = h1 @ W2cat + b2cat
    gemm_db_kernel<<<dim3(1, NN / 128), 256, GEMM_SMEM>>>(
        p_h1, p_W2, p_b2, p_AB2, 128, 128, 128, 0, 0, nullptr, nullptr,
        nullptr, nullptr, nullptr, 0);
    // agg2 + graph reduce + z build
    gnn_tail_kernel<<<NB, 256>>>(state, action, g2_w2, g2_b2);
    // Q layer 1 (both heads fused, Nc=512)
    gemm_db_kernel<<<dim3(4, NB / 128), 256, GEMM_SMEM>>>(
        p_z, p_QW1, p_Qb1, p_t1, 192, 512, 192, 1, 1, nullptr, nullptr,
        nullptr, nullptr, nullptr, 0);
    // Q layer 2 (z-batched heads)
    gemm_db_kernel<<<dim3(2, NB / 128, 2), 256, GEMM_SMEM>>>(
        p_t1, p_QW2a, q1_b2, p_t2, 256, 256, 512, 1, 0, nullptr, nullptr,
        p_QW2b, q2_b2, p_t2 + NB * 256, 256);
    qdot_kernel<<<(2 * NB * 32) / 256, 256>>>(q1_w3, q1_b3, q2_w3, q2_b3, out);
}